// round 12
// baseline (speedup 1.0000x reference)
#include <cuda_runtime.h>
#include <math.h>
#include <math_constants.h>

#define BATCH 64
#define DIM   768
#define HW    3136          // 56*56
#define FREQ  256
#define NE    16
#define TOPK  4

// scratch (device global: zero-initialized; finish kernel restores zeros)
__device__ float g_logits_main[BATCH * NE];   // atomic-accumulated pooled @ gate_w.T

// ---------------------------------------------------------------------------
// Kernel A (primary): streaming pool + gating GEMM ONLY (freq GEMM moved to
// the PDL dependent's prelude — it doesn't depend on x). Body otherwise
// identical to the R10 champion: one warp per (b,d) row, 8-deep ldcs batches,
// early launch_dependents fire.
// ---------------------------------------------------------------------------
__global__ void __launch_bounds__(256) pool_gate_kernel(
    const float* __restrict__ x,
    const float* __restrict__ gate_w) {

    // fire ASAP: dependent may launch once the last wave has STARTED
    asm volatile("griddepcontrol.launch_dependents;" ::: "memory");

    const int warp_id = (blockIdx.x * blockDim.x + threadIdx.x) >> 5;
    const int lane = threadIdx.x & 31;
    const int b = warp_id / DIM;
    const int d = warp_id - b * DIM;

    const float4* row = reinterpret_cast<const float4*>(x + (size_t)warp_id * HW);
    float s = 0.0f;
#pragma unroll
    for (int t = 0; t < 3; ++t) {           // 784 float4: 3 x (8 x 32 lanes) + 16
        float4 v[8];
#pragma unroll
        for (int k = 0; k < 8; ++k)
            v[k] = __ldcs(&row[lane + 32 * (t * 8 + k)]);
#pragma unroll
        for (int k = 0; k < 8; ++k)
            s += (v[k].x + v[k].y) + (v[k].z + v[k].w);
    }
    if (lane < 16) {
        float4 v = __ldcs(&row[768 + lane]);
        s += (v.x + v.y) + (v.z + v.w);
    }
#pragma unroll
    for (int m = 16; m; m >>= 1) s += __shfl_xor_sync(0xffffffffu, s, m);

    const float pooled = s * (1.0f / (float)HW);
    if (lane < NE)
        atomicAdd(&g_logits_main[b * NE + lane], pooled * gate_w[lane * DIM + d]);
}

// ---------------------------------------------------------------------------
// Kernel B (PDL secondary): prelude computes the ENTIRE freq-emb GEMM
// (independent of the primary) while the pool drains, then parks in
// cudaGridDependencySynchronize (HW wait) and runs the epilogue.
// Output (float32): gates[64*16] | top_k_indices[64*4] | top_k_values[64*4] | aux_loss
// ---------------------------------------------------------------------------
__global__ void finish_kernel(const float* __restrict__ noise,
                              const float* __restrict__ complexity,
                              const float* __restrict__ freq_emb,
                              const float* __restrict__ fgate_w,
                              float* __restrict__ out) {
    __shared__ float s_clean[BATCH * NE];
    __shared__ float s_p[BATCH * NE];

    const int tid  = threadIdx.x;          // 0..1023
    const int b    = tid >> 4;
    const int e    = tid & 15;
    const int lane = tid & 31;
    const int half = lane & 16;            // base lane of my 16-lane group

    // ---- prelude (all hidden under the pool drain via PDL) ----
    const float noise_std = 1.0f / (float)NE;
    const float my_noise  = noise[tid] * noise_std;
    const float my_cplx   = (tid < NE) ? complexity[tid] : 0.0f;

    // freq logit for my (b,e): dot(freq_emb[b,:], fgate_w[e,:]) over 256
    float fdot = 0.0f;
    {
        const float4* fr  = reinterpret_cast<const float4*>(freq_emb + b * FREQ);
        const float4* fgr = reinterpret_cast<const float4*>(fgate_w  + e * FREQ);
#pragma unroll
        for (int j = 0; j < FREQ / 4; ++j) {
            float4 a = fr[j];
            float4 w = fgr[j];
            fdot += a.x * w.x + a.y * w.y + a.z * w.z + a.w * w.w;
        }
    }

    // ---- HW wait for pool grid completion + memory visibility ----
    cudaGridDependencySynchronize();

    const float logit = g_logits_main[tid] + fdot;
    g_logits_main[tid] = 0.0f;             // restore for next replay (own element)
    const float noisy = logit + my_noise;

    // softmaxes without max-subtraction (logits O(10); ratio identical)
    float ce  = __expf(logit);
    float ne_ = __expf(noisy);
    float cs = ce, ns = ne_;
#pragma unroll
    for (int m = 8; m; m >>= 1) {
        cs += __shfl_xor_sync(0xffffffffu, cs, m);
        ns += __shfl_xor_sync(0xffffffffu, ns, m);
    }
    const float clean = ce / cs;
    const float score = ne_ / ns;

    // rank of my noisy logit within the row (ties: lower index wins, jax top_k)
    int rank = 0;
#pragma unroll
    for (int j = 0; j < 16; ++j) {
        float vj = __shfl_sync(0xffffffffu, noisy, half + j);
        rank += (vj > noisy) || (vj == noisy && j < e);
    }

    // threshold = k-th largest noisy logit (rank == TOPK-1)
    float thr = (rank == TOPK - 1) ? noisy : -CUDART_INF_F;
#pragma unroll
    for (int m = 8; m; m >>= 1) thr = fmaxf(thr, __shfl_xor_sync(0xffffffffu, thr, m));

    // outputs: gates / indices / values
    out[tid] = (rank < TOPK) ? score : 0.0f;
    if (rank < TOPK) {
        out[BATCH * NE + b * TOPK + rank]                 = (float)e;  // indices
        out[BATCH * NE + BATCH * TOPK + b * TOPK + rank]  = score;     // values
    }

    // p = 1 - norm_cdf((thr - logit)/noise_std)
    s_clean[tid] = clean;
    s_p[tid]     = 0.5f * erfcf((thr - logit) * (float)NE * 0.70710678118654752f);
    __syncthreads();

    // aux loss: fold 1024 -> 256 -> ... -> 16 (parallel tree over batch rows)
    if (tid < 256) {
        s_clean[tid] += s_clean[tid + 256] + s_clean[tid + 512] + s_clean[tid + 768];
        s_p[tid]     += s_p[tid + 256]     + s_p[tid + 512]     + s_p[tid + 768];
    }
    __syncthreads();
#pragma unroll
    for (int st = 128; st >= 16; st >>= 1) {
        if (tid < st) {
            s_clean[tid] += s_clean[tid + st];
            s_p[tid]     += s_p[tid + st];
        }
        __syncthreads();
    }

    if (tid < 32) {
        float imp = 0.0f, pm = 0.0f;
        if (tid < 16) {
            imp = s_clean[tid] * my_cplx;
            pm  = s_p[tid] * (1.0f / (float)BATCH);
        }
        float im = imp, pmn = pm;
#pragma unroll
        for (int m = 8; m; m >>= 1) {
            im  += __shfl_xor_sync(0xffffffffu, im,  m);
            pmn += __shfl_xor_sync(0xffffffffu, pmn, m);
        }
        im  *= (1.0f / (float)NE);
        pmn *= (1.0f / (float)NE);
        float dv = (tid < 16) ? (imp - im)  * (imp - im)  : 0.0f;
        float dp = (tid < 16) ? (pm  - pmn) * (pm  - pmn) : 0.0f;
#pragma unroll
        for (int m = 8; m; m >>= 1) {
            dv += __shfl_xor_sync(0xffffffffu, dv, m);
            dp += __shfl_xor_sync(0xffffffffu, dp, m);
        }
        if (tid == 0) {
            float imp_loss  = (dv / (float)(NE - 1)) / ((im  + 1e-8f) * (im  + 1e-8f));
            float load_loss = (dp / (float)(NE - 1)) / ((pmn + 1e-8f) * (pmn + 1e-8f));
            out[BATCH * NE + 2 * BATCH * TOPK] = 0.5f * imp_loss + 0.5f * load_loss;
        }
    }
}

// ---------------------------------------------------------------------------
extern "C" void kernel_launch(void* const* d_in, const int* in_sizes, int n_in,
                              void* d_out, int out_size) {
    const float* x          = (const float*)d_in[0];
    const float* freq_emb   = (const float*)d_in[1];
    const float* gate_w     = (const float*)d_in[2];
    const float* fgate_w    = (const float*)d_in[3];
    const float* complexity = (const float*)d_in[4];
    const float* noise      = (const float*)d_in[5];
    float* out = (float*)d_out;

    // A: streaming pool + gating GEMM — 6144 blocks, 8 warps each
    pool_gate_kernel<<<(BATCH * DIM) / 8, 256>>>(x, gate_w);

    // B: epilogue with programmatic dependent launch (early-fired);
    //    freq GEMM runs in its prelude, hidden under the pool drain.
    cudaLaunchAttribute attrs[1];
    attrs[0].id = cudaLaunchAttributeProgrammaticStreamSerialization;
    attrs[0].val.programmaticStreamSerializationAllowed = 1;

    cudaLaunchConfig_t cfg = {};
    cfg.gridDim  = dim3(1, 1, 1);
    cfg.blockDim = dim3(BATCH * NE, 1, 1);
    cfg.dynamicSmemBytes = 0;
    cfg.stream = 0;
    cfg.attrs = attrs;
    cfg.numAttrs = 1;

    cudaLaunchKernelEx(&cfg, finish_kernel, noise, complexity, freq_emb, fgate_w, out);
}

// round 13
// speedup vs baseline: 1.3709x; 1.3709x over previous
#include <cuda_runtime.h>
#include <math.h>
#include <math_constants.h>

#define BATCH 64
#define DIM   768
#define HW    3136          // 56*56
#define FREQ  256
#define NE    16
#define TOPK  4

// scratch (device globals: zero-initialized; finish kernel restores zeros)
__device__ float g_logits_main[BATCH * NE];   // atomic-accumulated pooled @ gate_w.T
__device__ float g_logits_freq[BATCH * NE];   // freq_emb @ freq_gate_w.T (plain writes)

// ---------------------------------------------------------------------------
// Kernel A (primary): streaming pool + gating GEMM. One warp per (b,d) row,
// 8-deep ldcs float4 batches (87% DRAM). freq GEMM rides on the d<16 warps —
// spread across the grid, NOT in the single-block epilogue (R12 lesson: one
// block = one SM's LSU = 35us for the same loads). Early PDL fire.
// ---------------------------------------------------------------------------
__global__ void __launch_bounds__(256) pool_gate_kernel(
    const float* __restrict__ x,
    const float* __restrict__ gate_w,
    const float* __restrict__ freq_emb,
    const float* __restrict__ fgate_w) {

    // fire ASAP: dependent may launch once the last wave has STARTED
    asm volatile("griddepcontrol.launch_dependents;" ::: "memory");

    const int warp_id = (blockIdx.x * blockDim.x + threadIdx.x) >> 5;
    const int lane = threadIdx.x & 31;
    const int b = warp_id / DIM;
    const int d = warp_id - b * DIM;

    const float4* row = reinterpret_cast<const float4*>(x + (size_t)warp_id * HW);
    float s = 0.0f;
#pragma unroll
    for (int t = 0; t < 3; ++t) {           // 784 float4: 3 x (8 x 32 lanes) + 16
        float4 v[8];
#pragma unroll
        for (int k = 0; k < 8; ++k)
            v[k] = __ldcs(&row[lane + 32 * (t * 8 + k)]);
#pragma unroll
        for (int k = 0; k < 8; ++k)
            s += (v[k].x + v[k].y) + (v[k].z + v[k].w);
    }
    if (lane < 16) {
        float4 v = __ldcs(&row[768 + lane]);
        s += (v.x + v.y) + (v.z + v.w);
    }
#pragma unroll
    for (int m = 16; m; m >>= 1) s += __shfl_xor_sync(0xffffffffu, s, m);

    const float pooled = s * (1.0f / (float)HW);
    if (lane < NE)
        atomicAdd(&g_logits_main[b * NE + lane], pooled * gate_w[lane * DIM + d]);

    if (d < NE) {                            // freq-emb logits ride along
        const int e = d;
        const float4* fr  = reinterpret_cast<const float4*>(freq_emb + b * FREQ);
        const float4* fgr = reinterpret_cast<const float4*>(fgate_w  + e * FREQ);
        float f = 0.0f;
#pragma unroll
        for (int j = 0; j < 2; ++j) {        // 64 float4 / 32 lanes
            float4 a = fr[lane + 32 * j];
            float4 w = fgr[lane + 32 * j];
            f += a.x * w.x + a.y * w.y + a.z * w.z + a.w * w.w;
        }
#pragma unroll
        for (int m = 16; m; m >>= 1) f += __shfl_xor_sync(0xffffffffu, f, m);
        if (lane == 0) g_logits_freq[b * NE + e] = f;
    }
}

// ---------------------------------------------------------------------------
// Kernel B (PDL secondary): ramps + preludes while the pool drains, parks in
// cudaGridDependencySynchronize (HW wait), then runs the epilogue.
// Output (float32): gates[64*16] | top_k_indices[64*4] | top_k_values[64*4] | aux_loss
// ---------------------------------------------------------------------------
__global__ void finish_kernel(const float* __restrict__ noise,
                              const float* __restrict__ complexity,
                              float* __restrict__ out) {
    __shared__ float s_clean[BATCH * NE];
    __shared__ float s_p[BATCH * NE];

    const int tid  = threadIdx.x;          // 0..1023
    const int b    = tid >> 4;
    const int e    = tid & 15;
    const int lane = tid & 31;
    const int half = lane & 16;            // base lane of my 16-lane group

    // ---- prelude: independent of the primary (overlaps pool drain) ----
    const float noise_std = 1.0f / (float)NE;
    const float my_noise  = noise[tid] * noise_std;
    const float my_cplx   = (tid < NE) ? complexity[tid] : 0.0f;

    // ---- HW wait for pool grid completion + memory visibility ----
    cudaGridDependencySynchronize();

    const float logit = g_logits_main[tid] + g_logits_freq[tid];
    g_logits_main[tid] = 0.0f;             // restore for next replay (own element)
    const float noisy = logit + my_noise;

    // softmaxes without max-subtraction (logits O(10); ratio identical)
    float ce  = __expf(logit);
    float ne_ = __expf(noisy);
    float cs = ce, ns = ne_;
#pragma unroll
    for (int m = 8; m; m >>= 1) {
        cs += __shfl_xor_sync(0xffffffffu, cs, m);
        ns += __shfl_xor_sync(0xffffffffu, ns, m);
    }
    const float clean = ce / cs;
    const float score = ne_ / ns;

    // rank of my noisy logit within the row (ties: lower index wins, jax top_k)
    int rank = 0;
#pragma unroll
    for (int j = 0; j < 16; ++j) {
        float vj = __shfl_sync(0xffffffffu, noisy, half + j);
        rank += (vj > noisy) || (vj == noisy && j < e);
    }

    // threshold = k-th largest noisy logit (rank == TOPK-1)
    float thr = (rank == TOPK - 1) ? noisy : -CUDART_INF_F;
#pragma unroll
    for (int m = 8; m; m >>= 1) thr = fmaxf(thr, __shfl_xor_sync(0xffffffffu, thr, m));

    // outputs: gates / indices / values
    out[tid] = (rank < TOPK) ? score : 0.0f;
    if (rank < TOPK) {
        out[BATCH * NE + b * TOPK + rank]                 = (float)e;  // indices
        out[BATCH * NE + BATCH * TOPK + b * TOPK + rank]  = score;     // values
    }

    // p = 1 - norm_cdf((thr - logit)/noise_std)
    s_clean[tid] = clean;
    s_p[tid]     = 0.5f * erfcf((thr - logit) * (float)NE * 0.70710678118654752f);
    __syncthreads();

    // aux loss: fold 1024 -> 256 -> ... -> 16 (parallel tree over batch rows)
    if (tid < 256) {
        s_clean[tid] += s_clean[tid + 256] + s_clean[tid + 512] + s_clean[tid + 768];
        s_p[tid]     += s_p[tid + 256]     + s_p[tid + 512]     + s_p[tid + 768];
    }
    __syncthreads();
#pragma unroll
    for (int st = 128; st >= 16; st >>= 1) {
        if (tid < st) {
            s_clean[tid] += s_clean[tid + st];
            s_p[tid]     += s_p[tid + st];
        }
        __syncthreads();
    }

    if (tid < 32) {
        float imp = 0.0f, pm = 0.0f;
        if (tid < 16) {
            imp = s_clean[tid] * my_cplx;
            pm  = s_p[tid] * (1.0f / (float)BATCH);
        }
        float im = imp, pmn = pm;
#pragma unroll
        for (int m = 8; m; m >>= 1) {
            im  += __shfl_xor_sync(0xffffffffu, im,  m);
            pmn += __shfl_xor_sync(0xffffffffu, pmn, m);
        }
        im  *= (1.0f / (float)NE);
        pmn *= (1.0f / (float)NE);
        float dv = (tid < 16) ? (imp - im)  * (imp - im)  : 0.0f;
        float dp = (tid < 16) ? (pm  - pmn) * (pm  - pmn) : 0.0f;
#pragma unroll
        for (int m = 8; m; m >>= 1) {
            dv += __shfl_xor_sync(0xffffffffu, dv, m);
            dp += __shfl_xor_sync(0xffffffffu, dp, m);
        }
        if (tid == 0) {
            float imp_loss  = (dv / (float)(NE - 1)) / ((im  + 1e-8f) * (im  + 1e-8f));
            float load_loss = (dp / (float)(NE - 1)) / ((pmn + 1e-8f) * (pmn + 1e-8f));
            out[BATCH * NE + 2 * BATCH * TOPK] = 0.5f * imp_loss + 0.5f * load_loss;
        }
    }
}

// ---------------------------------------------------------------------------
extern "C" void kernel_launch(void* const* d_in, const int* in_sizes, int n_in,
                              void* d_out, int out_size) {
    const float* x          = (const float*)d_in[0];
    const float* freq_emb   = (const float*)d_in[1];
    const float* gate_w     = (const float*)d_in[2];
    const float* fgate_w    = (const float*)d_in[3];
    const float* complexity = (const float*)d_in[4];
    const float* noise      = (const float*)d_in[5];
    float* out = (float*)d_out;

    // A: streaming pool + gating GEMM — 6144 blocks, 8 warps each
    pool_gate_kernel<<<(BATCH * DIM) / 8, 256>>>(x, gate_w, freq_emb, fgate_w);

    // B: epilogue with programmatic dependent launch (early-fired)
    cudaLaunchAttribute attrs[1];
    attrs[0].id = cudaLaunchAttributeProgrammaticStreamSerialization;
    attrs[0].val.programmaticStreamSerializationAllowed = 1;

    cudaLaunchConfig_t cfg = {};
    cfg.gridDim  = dim3(1, 1, 1);
    cfg.blockDim = dim3(BATCH * NE, 1, 1);
    cfg.dynamicSmemBytes = 0;
    cfg.stream = 0;
    cfg.attrs = attrs;
    cfg.numAttrs = 1;

    cudaLaunchKernelEx(&cfg, finish_kernel, noise, complexity, out);
}

// round 14
// speedup vs baseline: 1.3979x; 1.0197x over previous
#include <cuda_runtime.h>
#include <math.h>
#include <math_constants.h>

#define BATCH 64
#define DIM   768
#define HW    3136          // 56*56
#define FREQ  256
#define NE    16
#define TOPK  4

// scratch (device globals: zero-initialized; finish kernel restores zeros)
__device__ float g_logits_main[BATCH * NE];   // atomic-accumulated pooled @ gate_w.T
__device__ float g_logits_freq[BATCH * NE];   // freq_emb @ freq_gate_w.T (plain writes)

// ---------------------------------------------------------------------------
// Kernel A (primary): streaming pool + gating GEMM. One warp per (b,d) row,
// 8-deep ldcs float4 batches (87% DRAM). freq GEMM rides on the FIRST 1024
// warps (blocks 0..127 — all in wave 1 of 5.19), so the last partial wave —
// the blocks the PDL dependent actually waits on — carries no extra work.
// ---------------------------------------------------------------------------
__global__ void __launch_bounds__(256) pool_gate_kernel(
    const float* __restrict__ x,
    const float* __restrict__ gate_w,
    const float* __restrict__ freq_emb,
    const float* __restrict__ fgate_w) {

    // fire ASAP: dependent may launch once the last wave has STARTED
    asm volatile("griddepcontrol.launch_dependents;" ::: "memory");

    const int warp_id = (blockIdx.x * blockDim.x + threadIdx.x) >> 5;
    const int lane = threadIdx.x & 31;
    const int b = warp_id / DIM;
    const int d = warp_id - b * DIM;

    const float4* row = reinterpret_cast<const float4*>(x + (size_t)warp_id * HW);
    float s = 0.0f;
#pragma unroll
    for (int t = 0; t < 3; ++t) {           // 784 float4: 3 x (8 x 32 lanes) + 16
        float4 v[8];
#pragma unroll
        for (int k = 0; k < 8; ++k)
            v[k] = __ldcs(&row[lane + 32 * (t * 8 + k)]);
#pragma unroll
        for (int k = 0; k < 8; ++k)
            s += (v[k].x + v[k].y) + (v[k].z + v[k].w);
    }
    if (lane < 16) {
        float4 v = __ldcs(&row[768 + lane]);
        s += (v.x + v.y) + (v.z + v.w);
    }
#pragma unroll
    for (int m = 16; m; m >>= 1) s += __shfl_xor_sync(0xffffffffu, s, m);

    const float pooled = s * (1.0f / (float)HW);
    if (lane < NE)
        atomicAdd(&g_logits_main[b * NE + lane], pooled * gate_w[lane * DIM + d]);

    // freq-emb logits on the FIRST-WAVE warps only: (fb, fe) = (w>>4, w&15)
    if (warp_id < BATCH * NE) {
        const int fb = warp_id >> 4;
        const int fe = warp_id & 15;
        const float4* fr  = reinterpret_cast<const float4*>(freq_emb + fb * FREQ);
        const float4* fgr = reinterpret_cast<const float4*>(fgate_w  + fe * FREQ);
        float f = 0.0f;
#pragma unroll
        for (int j = 0; j < 2; ++j) {        // 64 float4 / 32 lanes
            float4 a = fr[lane + 32 * j];
            float4 w = fgr[lane + 32 * j];
            f += a.x * w.x + a.y * w.y + a.z * w.z + a.w * w.w;
        }
#pragma unroll
        for (int m = 16; m; m >>= 1) f += __shfl_xor_sync(0xffffffffu, f, m);
        if (lane == 0) g_logits_freq[warp_id] = f;
    }
}

// ---------------------------------------------------------------------------
// Kernel B (PDL secondary): ramps + preludes while the pool drains, parks in
// cudaGridDependencySynchronize (HW wait), then runs the epilogue.
// Output (float32): gates[64*16] | top_k_indices[64*4] | top_k_values[64*4] | aux_loss
// ---------------------------------------------------------------------------
__global__ void finish_kernel(const float* __restrict__ noise,
                              const float* __restrict__ complexity,
                              float* __restrict__ out) {
    __shared__ float s_clean[BATCH * NE];
    __shared__ float s_p[BATCH * NE];

    const int tid  = threadIdx.x;          // 0..1023
    const int b    = tid >> 4;
    const int e    = tid & 15;
    const int lane = tid & 31;
    const int half = lane & 16;            // base lane of my 16-lane group

    // ---- prelude: independent of the primary (overlaps pool drain) ----
    const float noise_std = 1.0f / (float)NE;
    const float my_noise  = noise[tid] * noise_std;
    const float my_cplx   = (tid < NE) ? complexity[tid] : 0.0f;

    // ---- HW wait for pool grid completion + memory visibility ----
    cudaGridDependencySynchronize();

    const float logit = g_logits_main[tid] + g_logits_freq[tid];
    g_logits_main[tid] = 0.0f;             // restore for next replay (own element)
    const float noisy = logit + my_noise;

    // softmaxes without max-subtraction (logits O(10); ratio identical)
    float ce  = __expf(logit);
    float ne_ = __expf(noisy);
    float cs = ce, ns = ne_;
#pragma unroll
    for (int m = 8; m; m >>= 1) {
        cs += __shfl_xor_sync(0xffffffffu, cs, m);
        ns += __shfl_xor_sync(0xffffffffu, ns, m);
    }
    const float clean = ce / cs;
    const float score = ne_ / ns;

    // rank of my noisy logit within the row (ties: lower index wins, jax top_k)
    int rank = 0;
#pragma unroll
    for (int j = 0; j < 16; ++j) {
        float vj = __shfl_sync(0xffffffffu, noisy, half + j);
        rank += (vj > noisy) || (vj == noisy && j < e);
    }

    // threshold = k-th largest noisy logit (rank == TOPK-1)
    float thr = (rank == TOPK - 1) ? noisy : -CUDART_INF_F;
#pragma unroll
    for (int m = 8; m; m >>= 1) thr = fmaxf(thr, __shfl_xor_sync(0xffffffffu, thr, m));

    // outputs: gates / indices / values
    out[tid] = (rank < TOPK) ? score : 0.0f;
    if (rank < TOPK) {
        out[BATCH * NE + b * TOPK + rank]                 = (float)e;  // indices
        out[BATCH * NE + BATCH * TOPK + b * TOPK + rank]  = score;     // values
    }

    // p = 1 - norm_cdf((thr - logit)/noise_std)
    s_clean[tid] = clean;
    s_p[tid]     = 0.5f * erfcf((thr - logit) * (float)NE * 0.70710678118654752f);
    __syncthreads();

    // aux loss: fold 1024 -> 256 -> ... -> 16 (parallel tree over batch rows)
    if (tid < 256) {
        s_clean[tid] += s_clean[tid + 256] + s_clean[tid + 512] + s_clean[tid + 768];
        s_p[tid]     += s_p[tid + 256]     + s_p[tid + 512]     + s_p[tid + 768];
    }
    __syncthreads();
#pragma unroll
    for (int st = 128; st >= 16; st >>= 1) {
        if (tid < st) {
            s_clean[tid] += s_clean[tid + st];
            s_p[tid]     += s_p[tid + st];
        }
        __syncthreads();
    }

    if (tid < 32) {
        float imp = 0.0f, pm = 0.0f;
        if (tid < 16) {
            imp = s_clean[tid] * my_cplx;
            pm  = s_p[tid] * (1.0f / (float)BATCH);
        }
        float im = imp, pmn = pm;
#pragma unroll
        for (int m = 8; m; m >>= 1) {
            im  += __shfl_xor_sync(0xffffffffu, im,  m);
            pmn += __shfl_xor_sync(0xffffffffu, pmn, m);
        }
        im  *= (1.0f / (float)NE);
        pmn *= (1.0f / (float)NE);
        float dv = (tid < 16) ? (imp - im)  * (imp - im)  : 0.0f;
        float dp = (tid < 16) ? (pm  - pmn) * (pm  - pmn) : 0.0f;
#pragma unroll
        for (int m = 8; m; m >>= 1) {
            dv += __shfl_xor_sync(0xffffffffu, dv, m);
            dp += __shfl_xor_sync(0xffffffffu, dp, m);
        }
        if (tid == 0) {
            float imp_loss  = (dv / (float)(NE - 1)) / ((im  + 1e-8f) * (im  + 1e-8f));
            float load_loss = (dp / (float)(NE - 1)) / ((pmn + 1e-8f) * (pmn + 1e-8f));
            out[BATCH * NE + 2 * BATCH * TOPK] = 0.5f * imp_loss + 0.5f * load_loss;
        }
    }
}

// ---------------------------------------------------------------------------
extern "C" void kernel_launch(void* const* d_in, const int* in_sizes, int n_in,
                              void* d_out, int out_size) {
    const float* x          = (const float*)d_in[0];
    const float* freq_emb   = (const float*)d_in[1];
    const float* gate_w     = (const float*)d_in[2];
    const float* fgate_w    = (const float*)d_in[3];
    const float* complexity = (const float*)d_in[4];
    const float* noise      = (const float*)d_in[5];
    float* out = (float*)d_out;

    // A: streaming pool + gating GEMM — 6144 blocks, 8 warps each
    pool_gate_kernel<<<(BATCH * DIM) / 8, 256>>>(x, gate_w, freq_emb, fgate_w);

    // B: epilogue with programmatic dependent launch (early-fired)
    cudaLaunchAttribute attrs[1];
    attrs[0].id = cudaLaunchAttributeProgrammaticStreamSerialization;
    attrs[0].val.programmaticStreamSerializationAllowed = 1;

    cudaLaunchConfig_t cfg = {};
    cfg.gridDim  = dim3(1, 1, 1);
    cfg.blockDim = dim3(BATCH * NE, 1, 1);
    cfg.dynamicSmemBytes = 0;
    cfg.stream = 0;
    cfg.attrs = attrs;
    cfg.numAttrs = 1;

    cudaLaunchKernelEx(&cfg, finish_kernel, noise, complexity, out);
}